// round 1
// baseline (speedup 1.0000x reference)
#include <cuda_runtime.h>

typedef unsigned long long u64;

#define TPB 128

// ---- shared memory layout (in floats) ----
#define OFF_W1   0                 // 54*128 = 6912   (s_w1[k*128+o] = fc1_w[o][k])
#define OFF_W2   6912              // 128*128 = 16384 (s_w2[k*128+o] = out_w[o][k])
#define OFF_B1   23296             // 128
#define OFF_B2   23424             // 128
#define OFF_C1W  23552             // 27
#define OFF_C1B  23580             // 3
#define OFF_C2W  23584             // 162
#define OFF_C2B  23748             // 6
#define OFF_P2   23756             // 128*55 = 7040  (per-thread row, stride 55 -> conflict-free)
#define OFF_H    30796             // 128*129 = 16512 (stride 129 -> conflict-free)
#define SMEM_FLOATS (30796 + 16512)
#define SMEM_BYTES (SMEM_FLOATS * 4)

__device__ __forceinline__ u64 dup2(float a) {
    u64 r;
    asm("mov.b64 %0, {%1, %1};" : "=l"(r) : "r"(__float_as_uint(a)));
    return r;
}
__device__ __forceinline__ void fma2(u64& acc, u64 a, u64 b) {
    asm("fma.rn.f32x2 %0, %1, %2, %0;" : "+l"(acc) : "l"(a), "l"(b));
}
__device__ __forceinline__ float2 unpack2(u64 v) {
    unsigned lo, hi;
    asm("mov.b64 {%0, %1}, %2;" : "=r"(lo), "=r"(hi) : "l"(v));
    return make_float2(__uint_as_float(lo), __uint_as_float(hi));
}

__global__ void __launch_bounds__(TPB)
net_kernel(const float* __restrict__ x,
           const float* __restrict__ c1w, const float* __restrict__ c1b,
           const float* __restrict__ c2w, const float* __restrict__ c2b,
           const float* __restrict__ w1,  const float* __restrict__ b1,
           const float* __restrict__ w2,  const float* __restrict__ b2,
           float* __restrict__ out, int nsamp)
{
    extern __shared__ float sm[];
    const int tid = threadIdx.x;

    // ---- stage weights into shared (fc weights transposed for packed-pair loads) ----
    for (int i = tid; i < 6912; i += TPB) {
        int o = i / 54, k = i - o * 54;
        sm[OFF_W1 + k * 128 + o] = w1[i];
    }
    for (int i = tid; i < 16384; i += TPB) {
        int o = i >> 7, k = i & 127;
        sm[OFF_W2 + k * 128 + o] = w2[i];
    }
    if (tid < 128) sm[OFF_B1 + tid] = b1[tid];
    if (tid < 128) sm[OFF_B2 + tid] = b2[tid];
    if (tid < 27)  sm[OFF_C1W + tid] = c1w[tid];
    if (tid < 3)   sm[OFF_C1B + tid] = c1b[tid];
    for (int i = tid; i < 162; i += TPB) sm[OFF_C2W + i] = c2w[i];
    if (tid < 6)   sm[OFF_C2B + tid] = c2b[tid];
    __syncthreads();

    const int sample = blockIdx.x * TPB + tid;
    if (sample >= nsamp) return;

    const float* xp = x + (long long)sample * 128;

    // ================= stage 1: conv1 (1->3ch, 3x3 pad1 on 12x12) + maxpool2 + relu =================
    float cw[27];
#pragma unroll
    for (int i = 0; i < 27; i++) cw[i] = sm[OFF_C1W + i];
    float cbv[3];
#pragma unroll
    for (int i = 0; i < 3; i++) cbv[i] = sm[OFF_C1B + i];

    float c1p[3][6][6];

#pragma unroll
    for (int py = 0; py < 6; py++) {
        // grid rows needed: 2py-1 .. 2py+2 (rows <0, ==11, ==12 are zero; row 10 has 8 valid cols)
        float ra[4][12];
#pragma unroll
        for (int j = 0; j < 4; j++) {
            const int r = 2 * py - 1 + j;
            if (r < 0 || r >= 11) {
#pragma unroll
                for (int c = 0; c < 12; c++) ra[j][c] = 0.0f;
            } else if (r == 10) {
#pragma unroll
                for (int c = 0; c < 8; c += 2) {
                    float2 v = *(const float2*)(xp + 120 + c);
                    ra[j][c] = v.x; ra[j][c + 1] = v.y;
                }
                ra[j][8] = 0.0f; ra[j][9] = 0.0f; ra[j][10] = 0.0f; ra[j][11] = 0.0f;
            } else {
#pragma unroll
                for (int c = 0; c < 12; c += 2) {
                    float2 v = *(const float2*)(xp + 12 * r + c);
                    ra[j][c] = v.x; ra[j][c + 1] = v.y;
                }
            }
        }
#pragma unroll
        for (int oc = 0; oc < 3; oc++) {
#pragma unroll
            for (int px = 0; px < 6; px++) {
                float s[2][2];
#pragma unroll
                for (int dy = 0; dy < 2; dy++) {
#pragma unroll
                    for (int dx = 0; dx < 2; dx++) {
                        float a = 0.0f;
                        const int ox = 2 * px + dx;
#pragma unroll
                        for (int ky = 0; ky < 3; ky++) {
#pragma unroll
                            for (int kx = 0; kx < 3; kx++) {
                                const int ix = ox + kx - 1;
                                if (ix >= 0 && ix < 12)
                                    a = fmaf(cw[oc * 9 + ky * 3 + kx], ra[dy + ky][ix], a);
                            }
                        }
                        s[dy][dx] = a;
                    }
                }
                float m = fmaxf(fmaxf(s[0][0], s[0][1]), fmaxf(s[1][0], s[1][1]));
                c1p[oc][py][px] = fmaxf(m + cbv[oc], 0.0f);
            }
        }
    }

    // ================= stage 2: conv2 (3->6ch, 3x3 pad1 on 6x6) + maxpool2 + relu -> p2[54] in smem =================
    for (int oc = 0; oc < 6; oc++) {       // rolled (p2 goes to shared)
        float w[27];
#pragma unroll
        for (int i = 0; i < 27; i++) w[i] = sm[OFF_C2W + oc * 27 + i];
        const float bb = sm[OFF_C2B + oc];
#pragma unroll
        for (int py = 0; py < 3; py++) {
#pragma unroll
            for (int px = 0; px < 3; px++) {
                float s[2][2];
#pragma unroll
                for (int dy = 0; dy < 2; dy++) {
#pragma unroll
                    for (int dx = 0; dx < 2; dx++) {
                        float a = 0.0f;
                        const int oy = 2 * py + dy, ox = 2 * px + dx;
#pragma unroll
                        for (int ic = 0; ic < 3; ic++) {
#pragma unroll
                            for (int ky = 0; ky < 3; ky++) {
#pragma unroll
                                for (int kx = 0; kx < 3; kx++) {
                                    const int iy = oy + ky - 1, ix = ox + kx - 1;
                                    if (iy >= 0 && iy < 6 && ix >= 0 && ix < 6)
                                        a = fmaf(w[ic * 9 + ky * 3 + kx], c1p[ic][iy][ix], a);
                                }
                            }
                        }
                        s[dy][dx] = a;
                    }
                }
                float m = fmaxf(fmaxf(s[0][0], s[0][1]), fmaxf(s[1][0], s[1][1]));
                sm[OFF_P2 + tid * 55 + oc * 9 + py * 3 + px] = fmaxf(m + bb, 0.0f);
            }
        }
    }

    // ================= stage 3: fc1 (54 -> 128) + relu, packed f32x2 over output pairs =================
    u64 acc[64];
    {
        const u64* bp = (const u64*)(sm + OFF_B1);
#pragma unroll
        for (int j = 0; j < 64; j++) acc[j] = bp[j];
    }
    const float* p2row = sm + OFF_P2 + tid * 55;
    for (int k = 0; k < 54; k++) {          // rolled
        const u64 xx = dup2(p2row[k]);
        const ulonglong2* wr = (const ulonglong2*)(sm + OFF_W1 + k * 128);
#pragma unroll
        for (int j2 = 0; j2 < 32; j2++) {
            ulonglong2 w = wr[j2];
            fma2(acc[2 * j2],     xx, w.x);
            fma2(acc[2 * j2 + 1], xx, w.y);
        }
    }
    float* hrow = sm + OFF_H + tid * 129;
#pragma unroll
    for (int j = 0; j < 64; j++) {
        float2 v = unpack2(acc[j]);
        hrow[2 * j]     = fmaxf(v.x, 0.0f);
        hrow[2 * j + 1] = fmaxf(v.y, 0.0f);
    }

    // ================= stage 4: out (128 -> 128), packed f32x2 =================
    {
        const u64* bp = (const u64*)(sm + OFF_B2);
#pragma unroll
        for (int j = 0; j < 64; j++) acc[j] = bp[j];
    }
    for (int k = 0; k < 128; k++) {         // rolled
        const u64 xx = dup2(hrow[k]);
        const ulonglong2* wr = (const ulonglong2*)(sm + OFF_W2 + k * 128);
#pragma unroll
        for (int j2 = 0; j2 < 32; j2++) {
            ulonglong2 w = wr[j2];
            fma2(acc[2 * j2],     xx, w.x);
            fma2(acc[2 * j2 + 1], xx, w.y);
        }
    }

    float* op = out + (long long)sample * 128;
#pragma unroll
    for (int j = 0; j < 32; j++) {
        ulonglong2 v;
        v.x = acc[2 * j];
        v.y = acc[2 * j + 1];
        *reinterpret_cast<ulonglong2*>(op + 4 * j) = v;   // 16B-aligned: op is 512B aligned
    }
}

extern "C" void kernel_launch(void* const* d_in, const int* in_sizes, int n_in,
                              void* d_out, int out_size)
{
    const float* x   = (const float*)d_in[0];
    const float* c1w = (const float*)d_in[1];
    const float* c1b = (const float*)d_in[2];
    const float* c2w = (const float*)d_in[3];
    const float* c2b = (const float*)d_in[4];
    const float* w1  = (const float*)d_in[5];
    const float* b1  = (const float*)d_in[6];
    const float* w2  = (const float*)d_in[7];
    const float* b2  = (const float*)d_in[8];
    float* out = (float*)d_out;

    const int nsamp = in_sizes[0] / 128;
    const int blocks = (nsamp + TPB - 1) / TPB;

    cudaFuncSetAttribute(net_kernel, cudaFuncAttributeMaxDynamicSharedMemorySize, SMEM_BYTES);
    net_kernel<<<blocks, TPB, SMEM_BYTES>>>(x, c1w, c1b, c2w, c2b, w1, b1, w2, b2, out, nsamp);
}

// round 2
// speedup vs baseline: 1.0666x; 1.0666x over previous
#include <cuda_runtime.h>

typedef unsigned long long u64;

#define TPB 256

// ---- shared memory layout (floats) ----
#define OFF_W1   0        // [54][128]  w1t[k*128+o]
#define OFF_W2   6912     // [128][128] w2t[k*128+o]
#define OFF_B1   23296    // 128
#define OFF_B2   23424    // 128
#define OFF_C1W  23552    // 27
#define OFF_C1B  23580    // 3
#define OFF_C2W  23584    // 162
#define OFF_C2B  23748    // 6
#define OFF_P2   23756    // [54][260]  p2[k][sample-in-block]
#define P2S      260
#define OFF_H    37796    // [128][132] h[k][sample-in-chunk]
#define HS       132
#define SMEM_FLOATS 54692
#define SMEM_BYTES (SMEM_FLOATS * 4)

__device__ __forceinline__ u64 dup2(float a) {
    u64 r;
    asm("mov.b64 %0, {%1, %1};" : "=l"(r) : "r"(__float_as_uint(a)));
    return r;
}
__device__ __forceinline__ u64 pack2(float lo, float hi) {
    u64 r;
    asm("mov.b64 %0, {%1, %2};" : "=l"(r) : "r"(__float_as_uint(lo)), "r"(__float_as_uint(hi)));
    return r;
}
__device__ __forceinline__ void fma2(u64& acc, u64 a, u64 b) {
    asm("fma.rn.f32x2 %0, %1, %2, %0;" : "+l"(acc) : "l"(a), "l"(b));
}
__device__ __forceinline__ float2 unpack2(u64 v) {
    unsigned lo, hi;
    asm("mov.b64 {%0, %1}, %2;" : "=r"(lo), "=r"(hi) : "l"(v));
    return make_float2(__uint_as_float(lo), __uint_as_float(hi));
}

__global__ void __launch_bounds__(TPB)
net_kernel(const float* __restrict__ x,
           const float* __restrict__ c1w, const float* __restrict__ c1b,
           const float* __restrict__ c2w, const float* __restrict__ c2b,
           const float* __restrict__ w1,  const float* __restrict__ b1,
           const float* __restrict__ w2,  const float* __restrict__ b2,
           float* __restrict__ out, int nsamp)
{
    extern __shared__ float sm[];
    const int tid = threadIdx.x;

    // ---- stage weights (fc weights transposed: [k][o]) ----
    for (int i = tid; i < 6912; i += TPB) {
        int o = i / 54, k = i - o * 54;
        sm[OFF_W1 + k * 128 + o] = w1[i];
    }
    for (int i = tid; i < 16384; i += TPB) {
        int o = i >> 7, k = i & 127;
        sm[OFF_W2 + k * 128 + o] = w2[i];
    }
    if (tid < 128) { sm[OFF_B1 + tid] = b1[tid]; sm[OFF_B2 + tid] = b2[tid]; }
    if (tid < 27)  sm[OFF_C1W + tid] = c1w[tid];
    if (tid < 3)   sm[OFF_C1B + tid] = c1b[tid];
    if (tid < 162) sm[OFF_C2W + tid] = c2w[tid];
    if (tid < 6)   sm[OFF_C2B + tid] = c2b[tid];
    __syncthreads();

    const long long sample = (long long)blockIdx.x * TPB + tid;
    const bool valid = sample < nsamp;

    // ================= conv phase: 1 thread = 1 sample =================
    if (valid) {
        const float* xp = x + sample * 128;

        // ---- conv1 (1->3, 3x3 pad1 on 12x12) + maxpool2 + relu, dy-packed f32x2 ----
        float c1p[3][6][6];
#pragma unroll
        for (int py = 0; py < 6; py++) {
            float ra[4][12];
#pragma unroll
            for (int j = 0; j < 4; j++) {
                const int r = 2 * py - 1 + j;
                if (r < 0 || r >= 11) {
#pragma unroll
                    for (int c = 0; c < 12; c++) ra[j][c] = 0.0f;
                } else if (r == 10) {
#pragma unroll
                    for (int c = 0; c < 8; c += 2) {
                        float2 v = *(const float2*)(xp + 120 + c);
                        ra[j][c] = v.x; ra[j][c + 1] = v.y;
                    }
                    ra[j][8] = 0.0f; ra[j][9] = 0.0f; ra[j][10] = 0.0f; ra[j][11] = 0.0f;
                } else {
#pragma unroll
                    for (int c = 0; c < 12; c += 2) {
                        float2 v = *(const float2*)(xp + 12 * r + c);
                        ra[j][c] = v.x; ra[j][c + 1] = v.y;
                    }
                }
            }
            // pack row pairs: pr[ky][ix] = {ra[ky][ix] (dy=0), ra[ky+1][ix] (dy=1)}
            u64 pr[3][12];
#pragma unroll
            for (int j = 0; j < 3; j++)
#pragma unroll
                for (int ix = 0; ix < 12; ix++)
                    pr[j][ix] = pack2(ra[j][ix], ra[j + 1][ix]);

#pragma unroll
            for (int oc = 0; oc < 3; oc++) {
#pragma unroll
                for (int px = 0; px < 6; px++) {
                    u64 a0 = 0ull, a1 = 0ull;   // dx=0, dx=1 (lo=dy0, hi=dy1)
#pragma unroll
                    for (int ky = 0; ky < 3; ky++) {
#pragma unroll
                        for (int kx = 0; kx < 3; kx++) {
                            const u64 wd = dup2(sm[OFF_C1W + oc * 9 + ky * 3 + kx]);
                            const int ix0 = 2 * px + kx - 1;
                            const int ix1 = 2 * px + kx;
                            if (ix0 >= 0 && ix0 < 12) fma2(a0, wd, pr[ky][ix0]);
                            if (ix1 < 12)             fma2(a1, wd, pr[ky][ix1]);
                        }
                    }
                    float2 v0 = unpack2(a0), v1 = unpack2(a1);
                    float m = fmaxf(fmaxf(v0.x, v0.y), fmaxf(v1.x, v1.y));
                    c1p[oc][py][px] = fmaxf(m + sm[OFF_C1B + oc], 0.0f);
                }
            }
        }

        // ---- conv2 (3->6, 3x3 pad1 on 6x6) + maxpool2 + relu -> p2[k][tid], dy-packed ----
#pragma unroll
        for (int py = 0; py < 3; py++) {
            u64 acc[6][3][2];   // [oc][px][dx]
#pragma unroll
            for (int oc = 0; oc < 6; oc++)
#pragma unroll
                for (int px = 0; px < 3; px++) { acc[oc][px][0] = 0ull; acc[oc][px][1] = 0ull; }

#pragma unroll
            for (int ic = 0; ic < 3; ic++) {
                // pc[j][ix] = {c1p[ic][2py-1+j][ix] (dy=0), c1p[ic][2py+j][ix] (dy=1)}
                u64 pc[3][6];
#pragma unroll
                for (int j = 0; j < 3; j++) {
                    const int iy0 = 2 * py - 1 + j;
                    const int iy1 = 2 * py + j;
#pragma unroll
                    for (int ix = 0; ix < 6; ix++) {
                        const float lo = (iy0 >= 0 && iy0 < 6) ? c1p[ic][iy0][ix] : 0.0f;
                        const float hi = (iy1 < 6) ? c1p[ic][iy1][ix] : 0.0f;
                        pc[j][ix] = pack2(lo, hi);
                    }
                }
#pragma unroll
                for (int oc = 0; oc < 6; oc++) {
#pragma unroll
                    for (int ky = 0; ky < 3; ky++) {
#pragma unroll
                        for (int kx = 0; kx < 3; kx++) {
                            const u64 wd = dup2(sm[OFF_C2W + oc * 27 + ic * 9 + ky * 3 + kx]);
#pragma unroll
                            for (int px = 0; px < 3; px++) {
                                const int ix0 = 2 * px + kx - 1;
                                const int ix1 = 2 * px + kx;
                                if (ix0 >= 0 && ix0 < 6) fma2(acc[oc][px][0], wd, pc[ky][ix0]);
                                if (ix1 < 6)             fma2(acc[oc][px][1], wd, pc[ky][ix1]);
                            }
                        }
                    }
                }
            }
#pragma unroll
            for (int oc = 0; oc < 6; oc++) {
                const float bb = sm[OFF_C2B + oc];
#pragma unroll
                for (int px = 0; px < 3; px++) {
                    float2 v0 = unpack2(acc[oc][px][0]), v1 = unpack2(acc[oc][px][1]);
                    float m = fmaxf(fmaxf(v0.x, v0.y), fmaxf(v1.x, v1.y));
                    sm[OFF_P2 + (oc * 9 + py * 3 + px) * P2S + tid] = fmaxf(m + bb, 0.0f);
                }
            }
        }
    } else {
        for (int k = 0; k < 54; k++) sm[OFF_P2 + k * P2S + tid] = 0.0f;
    }
    __syncthreads();

    // ================= GEMM phases: 2 chunks of 128 samples =================
    const int sgrp = tid & 15;      // sample group: 8 samples each
    const int ogrp = tid >> 4;      // output group: 8 outputs each
    const int s0 = sgrp * 8;
    const int o0 = ogrp * 8;

#pragma unroll 1
    for (int c = 0; c < 2; c++) {
        const int sb = c * 128;

        // ---- fc1: [128 samp] x [54 -> 128], thread tile 8x8 ----
        u64 acc[8][4];
        {
            const u64* bp = (const u64*)(sm + OFF_B1 + o0);
            const u64 b0 = bp[0], b1v = bp[1], b2v = bp[2], b3v = bp[3];
#pragma unroll
            for (int i = 0; i < 8; i++) {
                acc[i][0] = b0; acc[i][1] = b1v; acc[i][2] = b2v; acc[i][3] = b3v;
            }
        }
        {
            const float* ap = sm + OFF_P2 + sb + s0;
            const float* wp = sm + OFF_W1 + o0;
#pragma unroll 2
            for (int k = 0; k < 54; k++) {
                const float4 av0 = *(const float4*)ap;
                const float4 av1 = *(const float4*)(ap + 4);
                const ulonglong2 wA = *(const ulonglong2*)wp;
                const ulonglong2 wB = *(const ulonglong2*)(wp + 4);
                u64 ad[8];
                ad[0] = dup2(av0.x); ad[1] = dup2(av0.y); ad[2] = dup2(av0.z); ad[3] = dup2(av0.w);
                ad[4] = dup2(av1.x); ad[5] = dup2(av1.y); ad[6] = dup2(av1.z); ad[7] = dup2(av1.w);
#pragma unroll
                for (int i = 0; i < 8; i++) {
                    fma2(acc[i][0], ad[i], wA.x);
                    fma2(acc[i][1], ad[i], wA.y);
                    fma2(acc[i][2], ad[i], wB.x);
                    fma2(acc[i][3], ad[i], wB.y);
                }
                ap += P2S; wp += 128;
            }
        }
        // relu -> h[o][s] (transposed store)
#pragma unroll
        for (int i = 0; i < 8; i++) {
#pragma unroll
            for (int j2 = 0; j2 < 4; j2++) {
                float2 v = unpack2(acc[i][j2]);
                sm[OFF_H + (o0 + 2 * j2)     * HS + s0 + i] = fmaxf(v.x, 0.0f);
                sm[OFF_H + (o0 + 2 * j2 + 1) * HS + s0 + i] = fmaxf(v.y, 0.0f);
            }
        }
        __syncthreads();

        // ---- out: [128 samp] x [128 -> 128], thread tile 8x8 ----
        {
            const u64* bp = (const u64*)(sm + OFF_B2 + o0);
            const u64 b0 = bp[0], b1v = bp[1], b2v = bp[2], b3v = bp[3];
#pragma unroll
            for (int i = 0; i < 8; i++) {
                acc[i][0] = b0; acc[i][1] = b1v; acc[i][2] = b2v; acc[i][3] = b3v;
            }
        }
        {
            const float* ap = sm + OFF_H + s0;
            const float* wp = sm + OFF_W2 + o0;
#pragma unroll 2
            for (int k = 0; k < 128; k++) {
                const float4 av0 = *(const float4*)ap;
                const float4 av1 = *(const float4*)(ap + 4);
                const ulonglong2 wA = *(const ulonglong2*)wp;
                const ulonglong2 wB = *(const ulonglong2*)(wp + 4);
                u64 ad[8];
                ad[0] = dup2(av0.x); ad[1] = dup2(av0.y); ad[2] = dup2(av0.z); ad[3] = dup2(av0.w);
                ad[4] = dup2(av1.x); ad[5] = dup2(av1.y); ad[6] = dup2(av1.z); ad[7] = dup2(av1.w);
#pragma unroll
                for (int i = 0; i < 8; i++) {
                    fma2(acc[i][0], ad[i], wA.x);
                    fma2(acc[i][1], ad[i], wA.y);
                    fma2(acc[i][2], ad[i], wB.x);
                    fma2(acc[i][3], ad[i], wB.y);
                }
                ap += HS; wp += 128;
            }
        }
        // store to gmem
#pragma unroll
        for (int i = 0; i < 8; i++) {
            const long long gs = (long long)blockIdx.x * TPB + sb + s0 + i;
            if (gs < nsamp) {
                float* op = out + gs * 128 + o0;
                ulonglong2 v0; v0.x = acc[i][0]; v0.y = acc[i][1];
                ulonglong2 v1; v1.x = acc[i][2]; v1.y = acc[i][3];
                *reinterpret_cast<ulonglong2*>(op)     = v0;
                *reinterpret_cast<ulonglong2*>(op + 4) = v1;
            }
        }
        __syncthreads();
    }
}

extern "C" void kernel_launch(void* const* d_in, const int* in_sizes, int n_in,
                              void* d_out, int out_size)
{
    const float* x   = (const float*)d_in[0];
    const float* c1w = (const float*)d_in[1];
    const float* c1b = (const float*)d_in[2];
    const float* c2w = (const float*)d_in[3];
    const float* c2b = (const float*)d_in[4];
    const float* w1  = (const float*)d_in[5];
    const float* b1  = (const float*)d_in[6];
    const float* w2  = (const float*)d_in[7];
    const float* b2  = (const float*)d_in[8];
    float* out = (float*)d_out;

    const int nsamp = in_sizes[0] / 128;
    const int blocks = (nsamp + TPB - 1) / TPB;

    cudaFuncSetAttribute(net_kernel, cudaFuncAttributeMaxDynamicSharedMemorySize, SMEM_BYTES);
    net_kernel<<<blocks, TPB, SMEM_BYTES>>>(x, c1w, c1b, c2w, c2b, w1, b1, w2, b2, out, nsamp);
}